// round 1
// baseline (speedup 1.0000x reference)
#include <cuda_runtime.h>
#include <cuda_bf16.h>
#include <cstdint>

// Problem constants (from reference)
#define N_NODES_MAX 50000
#define D_FEAT      128
#define HIDDEN      256
#define K_DIM       256   // 2*D_FEAT

// Scratch: segment sums and counts (device globals — no allocation allowed)
__device__ float g_sums[N_NODES_MAX * D_FEAT];   // 25.6 MB
__device__ float g_counts[N_NODES_MAX];          // 0.2 MB

// ---------------------------------------------------------------------------
// Kernel 1: zero the scratch
// ---------------------------------------------------------------------------
__global__ void zero_kernel(int M) {
    const int total4 = (M * D_FEAT) / 4;   // float4 count for sums
    float4 z = make_float4(0.f, 0.f, 0.f, 0.f);
    float4* s4 = reinterpret_cast<float4*>(g_sums);
    for (int i = blockIdx.x * blockDim.x + threadIdx.x; i < total4;
         i += gridDim.x * blockDim.x) {
        s4[i] = z;
    }
    for (int i = blockIdx.x * blockDim.x + threadIdx.x; i < M;
         i += gridDim.x * blockDim.x) {
        g_counts[i] = 0.f;
    }
}

// ---------------------------------------------------------------------------
// Kernel 2: edge scatter. One warp per edge; lane l handles 4 features via
// red.global.add.v4.f32 (no-return vector reduction, sm_90+). 19.2M reds
// instead of 76.8M scalar atomics.
// ---------------------------------------------------------------------------
__global__ void scatter_kernel(const float* __restrict__ nodes,
                               const int* __restrict__ senders,
                               const int* __restrict__ receivers,
                               int E) {
    int warp = (blockIdx.x * blockDim.x + threadIdx.x) >> 5;
    int lane = threadIdx.x & 31;
    if (warp >= E) return;
    int s = senders[warp];
    int r = receivers[warp];
    const float4* src = reinterpret_cast<const float4*>(nodes + (size_t)s * D_FEAT);
    float4 v = src[lane];   // lane*16 bytes, 32 lanes * 16B = 512B = full row
    float* dst = g_sums + (size_t)r * D_FEAT + lane * 4;
    asm volatile("red.global.add.v4.f32 [%0], {%1, %2, %3, %4};"
                 :: "l"(dst), "f"(v.x), "f"(v.y), "f"(v.z), "f"(v.w)
                 : "memory");
    if (lane == 0) {
        atomicAdd(g_counts + r, 1.0f);   // compiles to RED (no return used)
    }
}

// ---------------------------------------------------------------------------
// Kernel 3: fused (mean + concat + GEMM + bias + relu).
//   C[m][n] = relu( b[n] + sum_k h[m][k] * W[k][n] )
//   h[m][k] = sums[m][k] / max(counts[m],1)   for k <  128
//           = nodes[m][k-128]                  for k >= 128
// Classic SGEMM tiling: BM=128, BN=64, BK=16, 256 threads, 8x4 per thread.
// Mean-divide is fused into the A-tile load (no h_buf materialization).
// ---------------------------------------------------------------------------
#define BM 128
#define BN 64
#define BK 16

__global__ __launch_bounds__(256)
void gemm_kernel(const float* __restrict__ nodes,
                 const float* __restrict__ W,
                 const float* __restrict__ bias,
                 float* __restrict__ C,
                 int M) {
    __shared__ float As[BK][BM];
    __shared__ float Bs[BK][BN];

    const int tid = threadIdx.x;
    const int block_m = blockIdx.x * BM;
    const int block_n = blockIdx.y * BN;

    const int tm = tid >> 4;   // 0..15 -> rows tm*8 .. tm*8+7
    const int tn = tid & 15;   // 0..15 -> cols tn*4 .. tn*4+3

    float acc[8][4];
#pragma unroll
    for (int i = 0; i < 8; i++)
#pragma unroll
        for (int j = 0; j < 4; j++) acc[i][j] = 0.f;

    for (int k0 = 0; k0 < K_DIM; k0 += BK) {
        // ---- load A tile: 128 rows x 16 cols = 512 float4, 2 per thread ----
#pragma unroll
        for (int i = 0; i < 2; i++) {
            int f   = tid + i * 256;
            int row = f >> 2;              // 0..127
            int c4  = (f & 3) << 2;        // 0,4,8,12
            int gm  = block_m + row;
            float4 v = make_float4(0.f, 0.f, 0.f, 0.f);
            if (gm < M) {
                int k = k0 + c4;
                if (k < D_FEAT) {
                    // aggregated-mean half: sums / max(counts,1)
                    float cnt = g_counts[gm];
                    float rcp = 1.0f / fmaxf(cnt, 1.0f);
                    const float4 sv = *reinterpret_cast<const float4*>(
                        g_sums + (size_t)gm * D_FEAT + k);
                    v = make_float4(sv.x * rcp, sv.y * rcp, sv.z * rcp, sv.w * rcp);
                } else {
                    // self-features half
                    v = *reinterpret_cast<const float4*>(
                        nodes + (size_t)gm * D_FEAT + (k - D_FEAT));
                }
            }
            As[c4 + 0][row] = v.x;
            As[c4 + 1][row] = v.y;
            As[c4 + 2][row] = v.z;
            As[c4 + 3][row] = v.w;
        }
        // ---- load B tile: 16 rows x 64 cols = 256 float4, 1 per thread ----
        {
            int row = tid >> 4;            // 0..15
            int col = (tid & 15) << 2;     // 0..60
            float4 v = *reinterpret_cast<const float4*>(
                W + (size_t)(k0 + row) * HIDDEN + block_n + col);
            *reinterpret_cast<float4*>(&Bs[row][col]) = v;
        }
        __syncthreads();

#pragma unroll
        for (int k = 0; k < BK; k++) {
            float a[8], bb[4];
#pragma unroll
            for (int i = 0; i < 8; i++) a[i] = As[k][tm * 8 + i];
#pragma unroll
            for (int j = 0; j < 4; j++) bb[j] = Bs[k][tn * 4 + j];
#pragma unroll
            for (int i = 0; i < 8; i++)
#pragma unroll
                for (int j = 0; j < 4; j++) acc[i][j] += a[i] * bb[j];
        }
        __syncthreads();
    }

    // ---- epilogue: bias + relu ----
    float bb[4];
#pragma unroll
    for (int j = 0; j < 4; j++) bb[j] = bias[block_n + tn * 4 + j];

#pragma unroll
    for (int i = 0; i < 8; i++) {
        int gm = block_m + tm * 8 + i;
        if (gm < M) {
            float4 o;
            o.x = fmaxf(acc[i][0] + bb[0], 0.f);
            o.y = fmaxf(acc[i][1] + bb[1], 0.f);
            o.z = fmaxf(acc[i][2] + bb[2], 0.f);
            o.w = fmaxf(acc[i][3] + bb[3], 0.f);
            *reinterpret_cast<float4*>(C + (size_t)gm * HIDDEN + block_n + tn * 4) = o;
        }
    }
}

// ---------------------------------------------------------------------------
extern "C" void kernel_launch(void* const* d_in, const int* in_sizes, int n_in,
                              void* d_out, int out_size) {
    const float* nodes     = (const float*)d_in[0];
    const int*   senders   = (const int*)d_in[1];
    const int*   receivers = (const int*)d_in[2];
    const float* W         = (const float*)d_in[3];
    const float* bias      = (const float*)d_in[4];
    float*       out       = (float*)d_out;

    const int M = in_sizes[0] / D_FEAT;   // 50000
    const int E = in_sizes[1];            // 600000

    // 1) zero scratch
    zero_kernel<<<1024, 256>>>(M);

    // 2) edge scatter: 1 warp per edge, 8 warps per block
    int blocks = (E + 7) / 8;
    scatter_kernel<<<blocks, 256>>>(nodes, senders, receivers, E);

    // 3) fused mean+concat+GEMM+bias+relu
    dim3 grid((M + BM - 1) / BM, HIDDEN / BN);
    gemm_kernel<<<grid, 256>>>(nodes, W, bias, out, M);
}

// round 7
// speedup vs baseline: 1.6473x; 1.6473x over previous
#include <cuda_runtime.h>
#include <cuda_bf16.h>
#include <cstdint>

#define N_NODES_MAX 50000
#define D_FEAT      128
#define HIDDEN      256
#define K_DIM       256   // 2*D_FEAT

__device__ float g_sums[N_NODES_MAX * D_FEAT];   // 25.6 MB
__device__ float g_counts[N_NODES_MAX];          // 0.2 MB

// ---------------------------------------------------------------------------
// Kernel 1: zero the scratch
// ---------------------------------------------------------------------------
__global__ void zero_kernel(int M) {
    const int total4 = (M * D_FEAT) / 4;
    float4 z = make_float4(0.f, 0.f, 0.f, 0.f);
    float4* s4 = reinterpret_cast<float4*>(g_sums);
    for (int i = blockIdx.x * blockDim.x + threadIdx.x; i < total4;
         i += gridDim.x * blockDim.x) {
        s4[i] = z;
    }
    for (int i = blockIdx.x * blockDim.x + threadIdx.x; i < M;
         i += gridDim.x * blockDim.x) {
        g_counts[i] = 0.f;
    }
}

// ---------------------------------------------------------------------------
// Kernel 2: edge scatter. One warp per edge; red.global.add.v4.f32.
// ---------------------------------------------------------------------------
__global__ void scatter_kernel(const float* __restrict__ nodes,
                               const int* __restrict__ senders,
                               const int* __restrict__ receivers,
                               int E) {
    int warp = (blockIdx.x * blockDim.x + threadIdx.x) >> 5;
    int lane = threadIdx.x & 31;
    if (warp >= E) return;
    int s = senders[warp];
    int r = receivers[warp];
    const float4* src = reinterpret_cast<const float4*>(nodes + (size_t)s * D_FEAT);
    float4 v = src[lane];
    float* dst = g_sums + (size_t)r * D_FEAT + lane * 4;
    asm volatile("red.global.add.v4.f32 [%0], {%1, %2, %3, %4};"
                 :: "l"(dst), "f"(v.x), "f"(v.y), "f"(v.z), "f"(v.w)
                 : "memory");
    if (lane == 0) {
        atomicAdd(g_counts + r, 1.0f);
    }
}

// ---------------------------------------------------------------------------
// Kernel 3: fused mean+concat+GEMM+bias+relu with TF32 mma.sync tensor cores.
//   BM=128, BN=64, BK=32. 256 threads = 8 warps in a 4(m) x 2(n) grid.
//   Each warp computes a 32x32 output tile via 2x4 m16n8k8 mma tiles.
// ---------------------------------------------------------------------------
#define BM 128
#define BN 64
#define BK 32
#define AS_STRIDE 36   // 128 rows x 36 floats; (gid*4+tig) conflict-free
#define BS_STRIDE 72   // 32 rows x 72 floats; (tig*8+gid) conflict-free

__device__ __forceinline__ float to_tf32(float x) {
    float y;
    asm("cvt.rna.tf32.f32 %0, %1;" : "=f"(y) : "f"(x));
    return y;
}

__global__ __launch_bounds__(256)
void gemm_kernel(const float* __restrict__ nodes,
                 const float* __restrict__ W,
                 const float* __restrict__ bias,
                 float* __restrict__ C,
                 int M) {
    __shared__ float As[BM][AS_STRIDE];
    __shared__ float Bs[BK][BS_STRIDE];

    const int tid = threadIdx.x;
    const int lane = tid & 31;
    const int wid = tid >> 5;
    const int warp_m = wid >> 1;      // 0..3
    const int warp_n = wid & 1;       // 0..1
    const int gid = lane >> 2;        // 0..7 group id
    const int tig = lane & 3;         // 0..3 thread-in-group

    const int block_m = blockIdx.x * BM;
    const int block_n = blockIdx.y * BN;

    float c[2][4][4];
#pragma unroll
    for (int mt = 0; mt < 2; mt++)
#pragma unroll
        for (int nt = 0; nt < 4; nt++)
#pragma unroll
            for (int i = 0; i < 4; i++) c[mt][nt][i] = 0.f;

    for (int k0 = 0; k0 < K_DIM; k0 += BK) {
        // ---- A tile: 128 rows x 32 cols = 1024 float4; 4 per thread ----
#pragma unroll
        for (int i = 0; i < 4; i++) {
            int idx = tid + i * 256;
            int row = idx >> 3;             // 0..127
            int c4  = (idx & 7) << 2;       // 0,4,...,28
            int gm  = block_m + row;
            float4 v = make_float4(0.f, 0.f, 0.f, 0.f);
            if (gm < M) {
                if (k0 < D_FEAT) {
                    float cnt = g_counts[gm];
                    float rcp = 1.0f / fmaxf(cnt, 1.0f);
                    float4 sv = *reinterpret_cast<const float4*>(
                        g_sums + (size_t)gm * D_FEAT + k0 + c4);
                    v = make_float4(sv.x * rcp, sv.y * rcp, sv.z * rcp, sv.w * rcp);
                } else {
                    v = *reinterpret_cast<const float4*>(
                        nodes + (size_t)gm * D_FEAT + (k0 - D_FEAT) + c4);
                }
            }
            float4 t = make_float4(to_tf32(v.x), to_tf32(v.y),
                                   to_tf32(v.z), to_tf32(v.w));
            // byte addr row*144 + c4*4 : both multiples of 16 -> aligned
            *reinterpret_cast<float4*>(&As[row][c4]) = t;
        }
        // ---- B tile: 32 rows x 64 cols = 512 float4; 2 per thread ----
#pragma unroll
        for (int i = 0; i < 2; i++) {
            int idx = tid + i * 256;
            int row = idx >> 4;             // 0..31
            int c4  = (idx & 15) << 2;      // 0..60
            float4 v = *reinterpret_cast<const float4*>(
                W + (size_t)(k0 + row) * HIDDEN + block_n + c4);
            float4 t = make_float4(to_tf32(v.x), to_tf32(v.y),
                                   to_tf32(v.z), to_tf32(v.w));
            // byte addr row*288 + c4*4 : both multiples of 16 -> aligned
            *reinterpret_cast<float4*>(&Bs[row][c4]) = t;
        }
        __syncthreads();

#pragma unroll
        for (int kk = 0; kk < 4; kk++) {
            const int k = kk * 8;
            uint32_t a[2][4], b[4][2];
#pragma unroll
            for (int mt = 0; mt < 2; mt++) {
                int r = warp_m * 32 + mt * 16 + gid;
                a[mt][0] = __float_as_uint(As[r    ][k + tig    ]);
                a[mt][1] = __float_as_uint(As[r + 8][k + tig    ]);
                a[mt][2] = __float_as_uint(As[r    ][k + tig + 4]);
                a[mt][3] = __float_as_uint(As[r + 8][k + tig + 4]);
            }
#pragma unroll
            for (int nt = 0; nt < 4; nt++) {
                int col = warp_n * 32 + nt * 8 + gid;
                b[nt][0] = __float_as_uint(Bs[k + tig    ][col]);
                b[nt][1] = __float_as_uint(Bs[k + tig + 4][col]);
            }
#pragma unroll
            for (int mt = 0; mt < 2; mt++)
#pragma unroll
                for (int nt = 0; nt < 4; nt++) {
                    asm volatile(
                        "mma.sync.aligned.m16n8k8.row.col.f32.tf32.tf32.f32 "
                        "{%0,%1,%2,%3}, {%4,%5,%6,%7}, {%8,%9}, {%0,%1,%2,%3};"
                        : "+f"(c[mt][nt][0]), "+f"(c[mt][nt][1]),
                          "+f"(c[mt][nt][2]), "+f"(c[mt][nt][3])
                        : "r"(a[mt][0]), "r"(a[mt][1]), "r"(a[mt][2]), "r"(a[mt][3]),
                          "r"(b[nt][0]), "r"(b[nt][1]));
                }
        }
        __syncthreads();
    }

    // ---- epilogue: bias + relu, float2 stores ----
#pragma unroll
    for (int nt = 0; nt < 4; nt++) {
        int col = block_n + warp_n * 32 + nt * 8 + 2 * tig;
        float b0 = bias[col];
        float b1 = bias[col + 1];
#pragma unroll
        for (int mt = 0; mt < 2; mt++) {
            int r0 = block_m + warp_m * 32 + mt * 16 + gid;
            if (r0 < M) {
                float2 o;
                o.x = fmaxf(c[mt][nt][0] + b0, 0.f);
                o.y = fmaxf(c[mt][nt][1] + b1, 0.f);
                *reinterpret_cast<float2*>(C + (size_t)r0 * HIDDEN + col) = o;
            }
            int r1 = r0 + 8;
            if (r1 < M) {
                float2 o;
                o.x = fmaxf(c[mt][nt][2] + b0, 0.f);
                o.y = fmaxf(c[mt][nt][3] + b1, 0.f);
                *reinterpret_cast<float2*>(C + (size_t)r1 * HIDDEN + col) = o;
            }
        }
    }
}

// ---------------------------------------------------------------------------
extern "C" void kernel_launch(void* const* d_in, const int* in_sizes, int n_in,
                              void* d_out, int out_size) {
    const float* nodes     = (const float*)d_in[0];
    const int*   senders   = (const int*)d_in[1];
    const int*   receivers = (const int*)d_in[2];
    const float* W         = (const float*)d_in[3];
    const float* bias      = (const float*)d_in[4];
    float*       out       = (float*)d_out;

    const int M = in_sizes[0] / D_FEAT;   // 50000
    const int E = in_sizes[1];            // 600000

    zero_kernel<<<1024, 256>>>(M);

    int blocks = (E + 7) / 8;
    scatter_kernel<<<blocks, 256>>>(nodes, senders, receivers, E);

    dim3 grid((M + BM - 1) / BM, HIDDEN / BN);
    gemm_kernel<<<grid, 256>>>(nodes, W, bias, out, M);
}

// round 9
// speedup vs baseline: 1.7373x; 1.0546x over previous
#include <cuda_runtime.h>
#include <cuda_bf16.h>
#include <cstdint>

#define N_NODES_MAX 50000
#define D_FEAT      128
#define HIDDEN      256
#define K_DIM       256   // 2*D_FEAT

// Scratch (device globals — no allocation allowed)
__device__ float g_sums[N_NODES_MAX * D_FEAT];     // 25.6 MB
__device__ float g_counts[N_NODES_MAX];            // 0.2 MB
__device__ float g_h[N_NODES_MAX * K_DIM];         // 51.2 MB  tf32 [mean | nodes]
__device__ float g_W[K_DIM * HIDDEN];              // 0.26 MB  tf32 W

__device__ __forceinline__ float to_tf32(float x) {
    float y;
    asm("cvt.rna.tf32.f32 %0, %1;" : "=f"(y) : "f"(x));
    return y;
}

// ---------------------------------------------------------------------------
// Kernel 1: prep — zero scratch, pre-convert nodes -> g_h[:,128:], W -> g_W
// ---------------------------------------------------------------------------
__global__ void prep_kernel(const float* __restrict__ nodes,
                            const float* __restrict__ W, int M) {
    const int tid    = blockIdx.x * blockDim.x + threadIdx.x;
    const int stride = gridDim.x * blockDim.x;
    const int nf4    = (M * D_FEAT) / 4;

    float4* s4 = reinterpret_cast<float4*>(g_sums);
    const float4 z = make_float4(0.f, 0.f, 0.f, 0.f);
    for (int i = tid; i < nf4; i += stride) s4[i] = z;
    for (int i = tid; i < M; i += stride) g_counts[i] = 0.f;

    const float4* n4 = reinterpret_cast<const float4*>(nodes);
    for (int i = tid; i < nf4; i += stride) {
        int row = i >> 5;            // /32 float4 per node row
        int c   = (i & 31) << 2;
        float4 v = n4[i];
        float4 t = make_float4(to_tf32(v.x), to_tf32(v.y),
                               to_tf32(v.z), to_tf32(v.w));
        *reinterpret_cast<float4*>(g_h + (size_t)row * K_DIM + D_FEAT + c) = t;
    }

    const int w4 = (K_DIM * HIDDEN) / 4;
    const float4* W4 = reinterpret_cast<const float4*>(W);
    float4* gW4 = reinterpret_cast<float4*>(g_W);
    for (int i = tid; i < w4; i += stride) {
        float4 v = W4[i];
        gW4[i] = make_float4(to_tf32(v.x), to_tf32(v.y),
                             to_tf32(v.z), to_tf32(v.w));
    }
}

// ---------------------------------------------------------------------------
// Kernel 2: edge scatter. One warp per edge; red.global.add.v4.f32.
// ---------------------------------------------------------------------------
__global__ void scatter_kernel(const float* __restrict__ nodes,
                               const int* __restrict__ senders,
                               const int* __restrict__ receivers,
                               int E) {
    int warp = (blockIdx.x * blockDim.x + threadIdx.x) >> 5;
    int lane = threadIdx.x & 31;
    if (warp >= E) return;
    int s = senders[warp];
    int r = receivers[warp];
    const float4* src = reinterpret_cast<const float4*>(nodes + (size_t)s * D_FEAT);
    float4 v = src[lane];
    float* dst = g_sums + (size_t)r * D_FEAT + lane * 4;
    asm volatile("red.global.add.v4.f32 [%0], {%1, %2, %3, %4};"
                 :: "l"(dst), "f"(v.x), "f"(v.y), "f"(v.z), "f"(v.w)
                 : "memory");
    if (lane == 0) {
        atomicAdd(g_counts + r, 1.0f);
    }
}

// ---------------------------------------------------------------------------
// Kernel 3: normalize — g_h[:,:128] = tf32(g_sums / max(counts,1))
// ---------------------------------------------------------------------------
__global__ void normalize_kernel(int M) {
    int tid = blockIdx.x * blockDim.x + threadIdx.x;
    int total = (M * D_FEAT) / 4;
    if (tid >= total) return;
    int row = tid >> 5;
    int c   = (tid & 31) << 2;
    float rcp = 1.0f / fmaxf(g_counts[row], 1.0f);
    float4 s = *reinterpret_cast<const float4*>(g_sums + (size_t)row * D_FEAT + c);
    float4 t = make_float4(to_tf32(s.x * rcp), to_tf32(s.y * rcp),
                           to_tf32(s.z * rcp), to_tf32(s.w * rcp));
    *reinterpret_cast<float4*>(g_h + (size_t)row * K_DIM + c) = t;
}

// ---------------------------------------------------------------------------
// Kernel 4: GEMM C = relu(g_h @ g_W + b), TF32 mma.sync, cp.async 2-stage
// double-buffered mainloop. BM=128, BN=64, BK=32, 256 threads (8 warps,
// 4m x 2n), warp tile 32x32 via 2x4 m16n8k8.
// ---------------------------------------------------------------------------
#define BM 128
#define BN 64
#define BK 32
#define ASTR 36        // (36*r + c) mod 32 = 4r+c  -> conflict-free frag loads
#define BSTR 72        // (72*r + c) mod 32 = 8r+c  -> conflict-free frag loads
#define NTILES (K_DIM / BK)   // 8

#define AS_FLOATS (BM * ASTR)        // 4608
#define BS_FLOATS (BK * BSTR)        // 2304
#define SMEM_FLOATS (2 * (AS_FLOATS + BS_FLOATS))
#define SMEM_BYTES (SMEM_FLOATS * 4) // 55296

extern __shared__ float smem_dyn[];

__global__ __launch_bounds__(256)
void gemm_kernel(const float* __restrict__ bias,
                 float* __restrict__ C,
                 int M) {
    float* As = smem_dyn;                       // [2][BM][ASTR]
    float* Bs = smem_dyn + 2 * AS_FLOATS;       // [2][BK][BSTR]

    const int tid  = threadIdx.x;
    const int lane = tid & 31;
    const int wid  = tid >> 5;
    const int warp_m = wid >> 1;    // 0..3
    const int warp_n = wid & 1;     // 0..1
    const int gid = lane >> 2;      // 0..7
    const int tig = lane & 3;       // 0..3

    const int block_m = blockIdx.x * BM;
    const int block_n = blockIdx.y * BN;

    const uint32_t s_base = (uint32_t)__cvta_generic_to_shared(smem_dyn);

    // ---- async tile loader ----
    auto load_tiles = [&](int t, int stage) {
        const uint32_t a_base = s_base + (uint32_t)(stage * AS_FLOATS) * 4u;
        const uint32_t b_base = s_base + (uint32_t)(2 * AS_FLOATS + stage * BS_FLOATS) * 4u;
#pragma unroll
        for (int i = 0; i < 4; i++) {
            int idx = tid + i * 256;
            int row = idx >> 3;           // 0..127
            int c4  = (idx & 7) << 2;     // 0..28
            int gm  = block_m + row;
            int gmc = gm < M ? gm : 0;
            const float* src = g_h + (size_t)gmc * K_DIM + t * BK + c4;
            uint32_t dst = a_base + (uint32_t)(row * ASTR + c4) * 4u;
            int sz = (gm < M) ? 16 : 0;   // zero-fill OOB rows
            asm volatile("cp.async.cg.shared.global [%0], [%1], 16, %2;\n"
                         :: "r"(dst), "l"(src), "r"(sz));
        }
#pragma unroll
        for (int i = 0; i < 2; i++) {
            int idx = tid + i * 256;
            int row = idx >> 4;           // 0..31
            int c4  = (idx & 15) << 2;    // 0..60
            const float* src = g_W + (size_t)(t * BK + row) * HIDDEN + block_n + c4;
            uint32_t dst = b_base + (uint32_t)(row * BSTR + c4) * 4u;
            asm volatile("cp.async.cg.shared.global [%0], [%1], 16;\n"
                         :: "r"(dst), "l"(src));
        }
    };

    float c[2][4][4];
#pragma unroll
    for (int mt = 0; mt < 2; mt++)
#pragma unroll
        for (int nt = 0; nt < 4; nt++)
#pragma unroll
            for (int i = 0; i < 4; i++) c[mt][nt][i] = 0.f;

    // prologue: prefetch tile 0
    load_tiles(0, 0);
    asm volatile("cp.async.commit_group;\n" ::: "memory");

    for (int t = 0; t < NTILES; t++) {
        if (t + 1 < NTILES) {
            load_tiles(t + 1, (t + 1) & 1);
            asm volatile("cp.async.commit_group;\n" ::: "memory");
            asm volatile("cp.async.wait_group 1;\n" ::: "memory");
        } else {
            asm volatile("cp.async.wait_group 0;\n" ::: "memory");
        }
        __syncthreads();

        const float* Ab = As + (t & 1) * AS_FLOATS;
        const float* Bb = Bs + (t & 1) * BS_FLOATS;

#pragma unroll
        for (int kk = 0; kk < 4; kk++) {
            const int k = kk * 8;
            uint32_t a[2][4], b[4][2];
#pragma unroll
            for (int mt = 0; mt < 2; mt++) {
                int r = warp_m * 32 + mt * 16 + gid;
                a[mt][0] = __float_as_uint(Ab[(r    ) * ASTR + k + tig    ]);
                a[mt][1] = __float_as_uint(Ab[(r + 8) * ASTR + k + tig    ]);
                a[mt][2] = __float_as_uint(Ab[(r    ) * ASTR + k + tig + 4]);
                a[mt][3] = __float_as_uint(Ab[(r + 8) * ASTR + k + tig + 4]);
            }
#pragma unroll
            for (int nt = 0; nt < 4; nt++) {
                int col = warp_n * 32 + nt * 8 + gid;
                b[nt][0] = __float_as_uint(Bb[(k + tig    ) * BSTR + col]);
                b[nt][1] = __float_as_uint(Bb[(k + tig + 4) * BSTR + col]);
            }
#pragma unroll
            for (int mt = 0; mt < 2; mt++)
#pragma unroll
                for (int nt = 0; nt < 4; nt++) {
                    asm volatile(
                        "mma.sync.aligned.m16n8k8.row.col.f32.tf32.tf32.f32 "
                        "{%0,%1,%2,%3}, {%4,%5,%6,%7}, {%8,%9}, {%0,%1,%2,%3};"
                        : "+f"(c[mt][nt][0]), "+f"(c[mt][nt][1]),
                          "+f"(c[mt][nt][2]), "+f"(c[mt][nt][3])
                        : "r"(a[mt][0]), "r"(a[mt][1]), "r"(a[mt][2]), "r"(a[mt][3]),
                          "r"(b[nt][0]), "r"(b[nt][1]));
                }
        }
        __syncthreads();
    }

    // ---- epilogue: bias + relu, float2 stores ----
#pragma unroll
    for (int nt = 0; nt < 4; nt++) {
        int col = block_n + warp_n * 32 + nt * 8 + 2 * tig;
        float b0 = bias[col];
        float b1 = bias[col + 1];
#pragma unroll
        for (int mt = 0; mt < 2; mt++) {
            int r0 = block_m + warp_m * 32 + mt * 16 + gid;
            if (r0 < M) {
                float2 o;
                o.x = fmaxf(c[mt][nt][0] + b0, 0.f);
                o.y = fmaxf(c[mt][nt][1] + b1, 0.f);
                *reinterpret_cast<float2*>(C + (size_t)r0 * HIDDEN + col) = o;
            }
            int r1 = r0 + 8;
            if (r1 < M) {
                float2 o;
                o.x = fmaxf(c[mt][nt][2] + b0, 0.f);
                o.y = fmaxf(c[mt][nt][3] + b1, 0.f);
                *reinterpret_cast<float2*>(C + (size_t)r1 * HIDDEN + col) = o;
            }
        }
    }
}

// ---------------------------------------------------------------------------
extern "C" void kernel_launch(void* const* d_in, const int* in_sizes, int n_in,
                              void* d_out, int out_size) {
    const float* nodes     = (const float*)d_in[0];
    const int*   senders   = (const int*)d_in[1];
    const int*   receivers = (const int*)d_in[2];
    const float* W         = (const float*)d_in[3];
    const float* bias      = (const float*)d_in[4];
    float*       out       = (float*)d_out;

    const int M = in_sizes[0] / D_FEAT;   // 50000
    const int E = in_sizes[1];            // 600000

    // 1) prep: zero scratch + tf32 pre-conversion
    prep_kernel<<<2048, 256>>>(nodes, W, M);

    // 2) edge scatter
    int blocks = (E + 7) / 8;
    scatter_kernel<<<blocks, 256>>>(nodes, senders, receivers, E);

    // 3) normalize sums into g_h
    int nthreads = (M * D_FEAT) / 4;
    normalize_kernel<<<(nthreads + 255) / 256, 256>>>(M);

    // 4) GEMM (dynamic smem 55.3KB > 48KB default -> raise limit; host-side
    //    attribute set, immediate, graph-capture safe)
    static bool attr_set = false;
    if (!attr_set) {
        cudaFuncSetAttribute(gemm_kernel,
                             cudaFuncAttributeMaxDynamicSharedMemorySize,
                             SMEM_BYTES);
        attr_set = true;
    }
    dim3 grid((M + BM - 1) / BM, HIDDEN / BN);
    gemm_kernel<<<grid, 256, SMEM_BYTES>>>(bias, out, M);
}

// round 10
// speedup vs baseline: 2.2683x; 1.3056x over previous
#include <cuda_runtime.h>
#include <cuda_bf16.h>
#include <cstdint>

#define N_NODES_MAX 50000
#define E_MAX       620000
#define D_FEAT      128
#define HIDDEN      256
#define K_DIM       256   // 2*D_FEAT

// Scratch (device globals — no allocation allowed)
__device__ float g_h[N_NODES_MAX * K_DIM];   // 51.2 MB  tf32 [mean | nodes]
__device__ float g_W[K_DIM * HIDDEN];        // 0.26 MB  tf32 W
__device__ int   g_deg[N_NODES_MAX];         // receiver degrees
__device__ int   g_cur[N_NODES_MAX];         // fill cursors
__device__ int   g_off[N_NODES_MAX];         // CSR offsets (exclusive scan)
__device__ int   g_part[512];                // scan block partials
__device__ int   g_csr[E_MAX];               // sender idx grouped by receiver

__device__ __forceinline__ float to_tf32(float x) {
    float y;
    asm("cvt.rna.tf32.f32 %0, %1;" : "=f"(y) : "f"(x));
    return y;
}

// ---------------------------------------------------------------------------
// Kernel 1: prep — zero deg/cursors, convert nodes -> g_h[:,128:], W -> g_W
// ---------------------------------------------------------------------------
__global__ void prep_kernel(const float* __restrict__ nodes,
                            const float* __restrict__ W, int M) {
    const int tid    = blockIdx.x * blockDim.x + threadIdx.x;
    const int stride = gridDim.x * blockDim.x;

    for (int i = tid; i < M; i += stride) { g_deg[i] = 0; g_cur[i] = 0; }

    const int nf4 = (M * D_FEAT) / 4;
    const float4* n4 = reinterpret_cast<const float4*>(nodes);
    for (int i = tid; i < nf4; i += stride) {
        int row = i >> 5;            // 32 float4 per node row
        int c   = (i & 31) << 2;
        float4 v = n4[i];
        float4 t = make_float4(to_tf32(v.x), to_tf32(v.y),
                               to_tf32(v.z), to_tf32(v.w));
        *reinterpret_cast<float4*>(g_h + (size_t)row * K_DIM + D_FEAT + c) = t;
    }

    const int w4 = (K_DIM * HIDDEN) / 4;
    const float4* W4 = reinterpret_cast<const float4*>(W);
    float4* gW4 = reinterpret_cast<float4*>(g_W);
    for (int i = tid; i < w4; i += stride) {
        float4 v = W4[i];
        gW4[i] = make_float4(to_tf32(v.x), to_tf32(v.y),
                             to_tf32(v.z), to_tf32(v.w));
    }
}

// ---------------------------------------------------------------------------
// Kernel 2: receiver degrees (int atomics, ~12 avg collisions per addr)
// ---------------------------------------------------------------------------
__global__ void degree_kernel(const int* __restrict__ receivers, int E) {
    int e = blockIdx.x * blockDim.x + threadIdx.x;
    if (e < E) atomicAdd(&g_deg[receivers[e]], 1);
}

// ---------------------------------------------------------------------------
// Kernels 3a/3b/3c: exclusive scan of g_deg -> g_off (two-level, M <= 131072)
// ---------------------------------------------------------------------------
__global__ void scan1_kernel(int M) {
    __shared__ int s[256];
    int i = blockIdx.x * 256 + threadIdx.x;
    int v = (i < M) ? g_deg[i] : 0;
    s[threadIdx.x] = v;
    __syncthreads();
#pragma unroll
    for (int off = 1; off < 256; off <<= 1) {
        int t = (threadIdx.x >= off) ? s[threadIdx.x - off] : 0;
        __syncthreads();
        s[threadIdx.x] += t;
        __syncthreads();
    }
    if (i < M) g_off[i] = s[threadIdx.x] - v;         // exclusive within block
    if (threadIdx.x == 255) g_part[blockIdx.x] = s[255];  // block total
}

__global__ void scan2_kernel(int nblocks) {
    __shared__ int s[512];
    int v = (threadIdx.x < nblocks) ? g_part[threadIdx.x] : 0;
    s[threadIdx.x] = v;
    __syncthreads();
#pragma unroll
    for (int off = 1; off < 512; off <<= 1) {
        int t = (threadIdx.x >= off) ? s[threadIdx.x - off] : 0;
        __syncthreads();
        s[threadIdx.x] += t;
        __syncthreads();
    }
    if (threadIdx.x < nblocks) g_part[threadIdx.x] = s[threadIdx.x] - v;
}

__global__ void scan3_kernel(int M) {
    int i = blockIdx.x * 256 + threadIdx.x;
    if (i < M) g_off[i] += g_part[blockIdx.x];
}

// ---------------------------------------------------------------------------
// Kernel 4: fill CSR — csr[off[r] + cursor[r]++] = senders[e]
// ---------------------------------------------------------------------------
__global__ void fill_kernel(const int* __restrict__ senders,
                            const int* __restrict__ receivers, int E) {
    int e = blockIdx.x * blockDim.x + threadIdx.x;
    if (e >= E) return;
    int r = receivers[e];
    int pos = atomicAdd(&g_cur[r], 1);
    g_csr[g_off[r] + pos] = senders[e];
}

// ---------------------------------------------------------------------------
// Kernel 5: gather — one warp per node. Sum sender rows (plain L2 loads,
// NO atomics), mean, tf32, write into g_h[:, :128]. Fuses normalize.
// ---------------------------------------------------------------------------
__global__ void gather_kernel(const float* __restrict__ nodes, int M) {
    int warp = (blockIdx.x * blockDim.x + threadIdx.x) >> 5;
    int lane = threadIdx.x & 31;
    if (warp >= M) return;

    int deg  = g_deg[warp];
    int base = g_off[warp];
    const float4* n4 = reinterpret_cast<const float4*>(nodes);

    float4 a0 = make_float4(0.f, 0.f, 0.f, 0.f);
    float4 a1 = make_float4(0.f, 0.f, 0.f, 0.f);

    int j = 0;
    for (; j + 2 <= deg; j += 2) {
        int s0 = g_csr[base + j];
        int s1 = g_csr[base + j + 1];
        float4 v0 = n4[(size_t)s0 * 32 + lane];
        float4 v1 = n4[(size_t)s1 * 32 + lane];
        a0.x += v0.x; a0.y += v0.y; a0.z += v0.z; a0.w += v0.w;
        a1.x += v1.x; a1.y += v1.y; a1.z += v1.z; a1.w += v1.w;
    }
    if (j < deg) {
        int s0 = g_csr[base + j];
        float4 v0 = n4[(size_t)s0 * 32 + lane];
        a0.x += v0.x; a0.y += v0.y; a0.z += v0.z; a0.w += v0.w;
    }

    float rcp = 1.0f / fmaxf((float)deg, 1.0f);
    float4 t = make_float4(to_tf32((a0.x + a1.x) * rcp),
                           to_tf32((a0.y + a1.y) * rcp),
                           to_tf32((a0.z + a1.z) * rcp),
                           to_tf32((a0.w + a1.w) * rcp));
    *reinterpret_cast<float4*>(g_h + (size_t)warp * K_DIM + lane * 4) = t;
}

// ---------------------------------------------------------------------------
// Kernel 6: GEMM C = relu(g_h @ g_W + b), TF32 mma.sync, cp.async 2-stage.
// Unchanged from the 58.6us round-9 kernel.
// ---------------------------------------------------------------------------
#define BM 128
#define BN 64
#define BK 32
#define ASTR 36
#define BSTR 72
#define NTILES (K_DIM / BK)

#define AS_FLOATS (BM * ASTR)
#define BS_FLOATS (BK * BSTR)
#define SMEM_FLOATS (2 * (AS_FLOATS + BS_FLOATS))
#define SMEM_BYTES (SMEM_FLOATS * 4)

extern __shared__ float smem_dyn[];

__global__ __launch_bounds__(256)
void gemm_kernel(const float* __restrict__ bias,
                 float* __restrict__ C,
                 int M) {
    float* As = smem_dyn;
    float* Bs = smem_dyn + 2 * AS_FLOATS;

    const int tid  = threadIdx.x;
    const int lane = tid & 31;
    const int wid  = tid >> 5;
    const int warp_m = wid >> 1;
    const int warp_n = wid & 1;
    const int gid = lane >> 2;
    const int tig = lane & 3;

    const int block_m = blockIdx.x * BM;
    const int block_n = blockIdx.y * BN;

    const uint32_t s_base = (uint32_t)__cvta_generic_to_shared(smem_dyn);

    auto load_tiles = [&](int t, int stage) {
        const uint32_t a_base = s_base + (uint32_t)(stage * AS_FLOATS) * 4u;
        const uint32_t b_base = s_base + (uint32_t)(2 * AS_FLOATS + stage * BS_FLOATS) * 4u;
#pragma unroll
        for (int i = 0; i < 4; i++) {
            int idx = tid + i * 256;
            int row = idx >> 3;
            int c4  = (idx & 7) << 2;
            int gm  = block_m + row;
            int gmc = gm < M ? gm : 0;
            const float* src = g_h + (size_t)gmc * K_DIM + t * BK + c4;
            uint32_t dst = a_base + (uint32_t)(row * ASTR + c4) * 4u;
            int sz = (gm < M) ? 16 : 0;
            asm volatile("cp.async.cg.shared.global [%0], [%1], 16, %2;\n"
                         :: "r"(dst), "l"(src), "r"(sz));
        }
#pragma unroll
        for (int i = 0; i < 2; i++) {
            int idx = tid + i * 256;
            int row = idx >> 4;
            int c4  = (idx & 15) << 2;
            const float* src = g_W + (size_t)(t * BK + row) * HIDDEN + block_n + c4;
            uint32_t dst = b_base + (uint32_t)(row * BSTR + c4) * 4u;
            asm volatile("cp.async.cg.shared.global [%0], [%1], 16;\n"
                         :: "r"(dst), "l"(src));
        }
    };

    float c[2][4][4];
#pragma unroll
    for (int mt = 0; mt < 2; mt++)
#pragma unroll
        for (int nt = 0; nt < 4; nt++)
#pragma unroll
            for (int i = 0; i < 4; i++) c[mt][nt][i] = 0.f;

    load_tiles(0, 0);
    asm volatile("cp.async.commit_group;\n" ::: "memory");

    for (int t = 0; t < NTILES; t++) {
        if (t + 1 < NTILES) {
            load_tiles(t + 1, (t + 1) & 1);
            asm volatile("cp.async.commit_group;\n" ::: "memory");
            asm volatile("cp.async.wait_group 1;\n" ::: "memory");
        } else {
            asm volatile("cp.async.wait_group 0;\n" ::: "memory");
        }
        __syncthreads();

        const float* Ab = As + (t & 1) * AS_FLOATS;
        const float* Bb = Bs + (t & 1) * BS_FLOATS;

#pragma unroll
        for (int kk = 0; kk < 4; kk++) {
            const int k = kk * 8;
            uint32_t a[2][4], b[4][2];
#pragma unroll
            for (int mt = 0; mt < 2; mt++) {
                int r = warp_m * 32 + mt * 16 + gid;
                a[mt][0] = __float_as_uint(Ab[(r    ) * ASTR + k + tig    ]);
                a[mt][1] = __float_as_uint(Ab[(r + 8) * ASTR + k + tig    ]);
                a[mt][2] = __float_as_uint(Ab[(r    ) * ASTR + k + tig + 4]);
                a[mt][3] = __float_as_uint(Ab[(r + 8) * ASTR + k + tig + 4]);
            }
#pragma unroll
            for (int nt = 0; nt < 4; nt++) {
                int col = warp_n * 32 + nt * 8 + gid;
                b[nt][0] = __float_as_uint(Bb[(k + tig    ) * BSTR + col]);
                b[nt][1] = __float_as_uint(Bb[(k + tig + 4) * BSTR + col]);
            }
#pragma unroll
            for (int mt = 0; mt < 2; mt++)
#pragma unroll
                for (int nt = 0; nt < 4; nt++) {
                    asm volatile(
                        "mma.sync.aligned.m16n8k8.row.col.f32.tf32.tf32.f32 "
                        "{%0,%1,%2,%3}, {%4,%5,%6,%7}, {%8,%9}, {%0,%1,%2,%3};"
                        : "+f"(c[mt][nt][0]), "+f"(c[mt][nt][1]),
                          "+f"(c[mt][nt][2]), "+f"(c[mt][nt][3])
                        : "r"(a[mt][0]), "r"(a[mt][1]), "r"(a[mt][2]), "r"(a[mt][3]),
                          "r"(b[nt][0]), "r"(b[nt][1]));
                }
        }
        __syncthreads();
    }

#pragma unroll
    for (int nt = 0; nt < 4; nt++) {
        int col = block_n + warp_n * 32 + nt * 8 + 2 * tig;
        float b0 = bias[col];
        float b1 = bias[col + 1];
#pragma unroll
        for (int mt = 0; mt < 2; mt++) {
            int r0 = block_m + warp_m * 32 + mt * 16 + gid;
            if (r0 < M) {
                float2 o;
                o.x = fmaxf(c[mt][nt][0] + b0, 0.f);
                o.y = fmaxf(c[mt][nt][1] + b1, 0.f);
                *reinterpret_cast<float2*>(C + (size_t)r0 * HIDDEN + col) = o;
            }
            int r1 = r0 + 8;
            if (r1 < M) {
                float2 o;
                o.x = fmaxf(c[mt][nt][2] + b0, 0.f);
                o.y = fmaxf(c[mt][nt][3] + b1, 0.f);
                *reinterpret_cast<float2*>(C + (size_t)r1 * HIDDEN + col) = o;
            }
        }
    }
}

// ---------------------------------------------------------------------------
extern "C" void kernel_launch(void* const* d_in, const int* in_sizes, int n_in,
                              void* d_out, int out_size) {
    const float* nodes     = (const float*)d_in[0];
    const int*   senders   = (const int*)d_in[1];
    const int*   receivers = (const int*)d_in[2];
    const float* W         = (const float*)d_in[3];
    const float* bias      = (const float*)d_in[4];
    float*       out       = (float*)d_out;

    const int M = in_sizes[0] / D_FEAT;   // 50000
    const int E = in_sizes[1];            // 600000

    // 1) prep: zero deg/cur + tf32 pre-conversion of nodes & W
    prep_kernel<<<2048, 256>>>(nodes, W, M);

    // 2) CSR build: degrees -> exclusive scan -> fill
    degree_kernel<<<(E + 255) / 256, 256>>>(receivers, E);
    int nb = (M + 255) / 256;             // 196 for M=50000 (<=512 required)
    scan1_kernel<<<nb, 256>>>(M);
    scan2_kernel<<<1, 512>>>(nb);
    scan3_kernel<<<nb, 256>>>(M);
    fill_kernel<<<(E + 255) / 256, 256>>>(senders, receivers, E);

    // 3) gather + mean + tf32 into g_h[:, :128]  (no feature atomics)
    gather_kernel<<<(M * 32 + 255) / 256, 256>>>(nodes, M);

    // 4) GEMM
    static bool attr_set = false;
    if (!attr_set) {
        cudaFuncSetAttribute(gemm_kernel,
                             cudaFuncAttributeMaxDynamicSharedMemorySize,
                             SMEM_BYTES);
        attr_set = true;
    }
    dim3 grid((M + BM - 1) / BM, HIDDEN / BN);
    gemm_kernel<<<grid, 256, SMEM_BYTES>>>(bias, out, M);
}